// round 14
// baseline (speedup 1.0000x reference)
#include <cuda_runtime.h>
#include <math.h>
#include <stdint.h>

#define BB 64
#define EE 1024
#define HH 1024
#define LL 512
#define VV 50257
#define NBLK_OUT 393   // ceil(VV/128)

// ---------------- scratch (device globals, no allocation) ----------------
__device__ float g_attnapp[BB * HH];
__device__ float g_x[BB * EE];
__device__ float g_partA[16 * BB * EE];      // attn 16*64*512=524K, comb 8*64*1024=524K, gi 4*64*3072=786K (cap 1.05M)
__device__ float g_partB[12 * BB * EE];      // gh 4*64*3072 = 786,432 floats (cap 786,432 exact)
__device__ float g_pmax[64 * 512];
__device__ float g_psum[64 * 512];

// ---------------- helpers ----------------
__device__ __forceinline__ uint32_t pack_bf16(float lo, float hi) {
    uint32_t r;
    asm("cvt.rn.bf16x2.f32 %0, %1, %2;" : "=r"(r) : "f"(hi), "f"(lo));
    return r;
}
__device__ __forceinline__ int tile_off8(int row, int k) {
    int c = k >> 3;
    return (((row >> 3) << 3) + c) * 128 + (((row & 7) ^ c) << 4) + (k & 7) * 2;
}
__device__ __forceinline__ void split_store(char* hiP, char* loP, int off, float4 v) {
    uint32_t bx = __float_as_uint(v.x), by = __float_as_uint(v.y);
    uint32_t bz = __float_as_uint(v.z), bw = __float_as_uint(v.w);
    uint2 hi = make_uint2(__byte_perm(bx, by, 0x7632), __byte_perm(bz, bw, 0x7632));
    float lx = v.x - __uint_as_float(bx & 0xffff0000u);
    float ly = v.y - __uint_as_float(by & 0xffff0000u);
    float lz = v.z - __uint_as_float(bz & 0xffff0000u);
    float lw = v.w - __uint_as_float(bw & 0xffff0000u);
    uint2 lo = make_uint2(pack_bf16(lx, ly), pack_bf16(lz, lw));
    *reinterpret_cast<uint2*>(hiP + off) = hi;
    *reinterpret_cast<uint2*>(loP + off) = lo;
}
__device__ __forceinline__ void rn_store(char* P, int off, float4 v) {
    uint2 r = make_uint2(pack_bf16(v.x, v.y), pack_bf16(v.z, v.w));
    *reinterpret_cast<uint2*>(P + off) = r;
}

#define MMA_BF16(ac, a, b0, b1)                                                   \
    asm volatile("mma.sync.aligned.m16n8k16.row.col.f32.bf16.bf16.f32 "           \
                 "{%0,%1,%2,%3}, {%4,%5,%6,%7}, {%8,%9}, {%0,%1,%2,%3};"          \
                 : "+f"((ac)[0]), "+f"((ac)[1]), "+f"((ac)[2]), "+f"((ac)[3])     \
                 : "r"((a)[0]), "r"((a)[1]), "r"((a)[2]), "r"((a)[3]),            \
                   "r"(b0), "r"(b1))

// ================= split-bf16 tensor GEMM (split-K partials, 3-MMA) =================
// Two independent problems selected by blockIdx.z with per-problem grid bounds.
__global__ __launch_bounds__(256) void gemm_bf16s(
    const float* A1, const float* A2, const int* gids, int K1, int K,
    const float* W, float* C, int N, int kChunk, int gx, int gy,
    const float* A1b, const float* Wb, float* Cb, int Nb, int kChunkB, int Kb, int gxB, int gyB) {
    if (blockIdx.z == 1) {
        if ((int)blockIdx.x >= gxB || (int)blockIdx.y >= gyB) return;
        A1 = A1b; A2 = nullptr; gids = nullptr; K1 = Kb; K = Kb;
        W = Wb; C = Cb; N = Nb; kChunk = kChunkB;
    } else {
        if ((int)blockIdx.x >= gx || (int)blockIdx.y >= gy) return;
    }

    __shared__ __align__(16) uint32_t smAhi[2048], smAlo[2048];
    __shared__ __align__(16) uint32_t smBhi[4096], smBlo[4096];

    const int tid = threadIdx.x;
    const int lane = tid & 31, wid = tid >> 5;
    const int wm = wid & 1, wn = wid >> 1;
    const int nBase = blockIdx.x * 128;
    const int kBase = blockIdx.y * kChunk;
    const int tiles = kChunk >> 6;

    uint32_t aHi = (uint32_t)__cvta_generic_to_shared(smAhi);
    uint32_t aLo = (uint32_t)__cvta_generic_to_shared(smAlo);
    uint32_t bHi = (uint32_t)__cvta_generic_to_shared(smBhi);
    uint32_t bLo = (uint32_t)__cvta_generic_to_shared(smBlo);

    int aAtom[2], aLowr[2];
#pragma unroll
    for (int ma = 0; ma < 2; ma++) {
        int row = wm * 32 + ma * 16 + ((lane >> 3) & 1) * 8 + (lane & 7);
        aAtom[ma] = (row >> 3) << 10;
        aLowr[ma] = row & 7;
    }
    const int aCbit = lane >> 4;
    int bAtom[4], bLowr[4];
    const int ll = lane & 15;
#pragma unroll
    for (int na = 0; na < 4; na++) {
        int n = wn * 32 + na * 8 + (ll & 7);
        bAtom[na] = (n >> 3) << 10;
        bLowr[na] = n & 7;
    }
    const int bCbit = ll >> 3;

    float acc[2][4][4];
#pragma unroll
    for (int i = 0; i < 2; i++)
#pragma unroll
        for (int j = 0; j < 4; j++)
#pragma unroll
            for (int q = 0; q < 4; q++) acc[i][j][q] = 0.f;

    float4 ra[4], rb[8];
    const int arow = tid >> 4, ac4 = tid & 15;

    auto loadA = [&](int k0) {
#pragma unroll
        for (int s = 0; s < 4; s++) {
            int row = arow + 16 * s;
            int k = k0 + ac4 * 4;
            const float* rp;
            if (k < K1) rp = (gids ? A1 + (size_t)gids[row] * K1 : A1 + (size_t)row * K1) + k;
            else        rp = A2 + (size_t)row * (K - K1) + (k - K1);
            ra[s] = *reinterpret_cast<const float4*>(rp);
        }
    };
    auto loadB = [&](int k0) {
#pragma unroll
        for (int s = 0; s < 8; s++)
            rb[s] = __ldcs(reinterpret_cast<const float4*>(
                W + (size_t)(nBase + arow + 16 * s) * K + k0 + ac4 * 4));
    };

    loadA(kBase);
    loadB(kBase);

    for (int kt = 0; kt < tiles; kt++) {
        __syncthreads();
#pragma unroll
        for (int s = 0; s < 4; s++)
            split_store((char*)smAhi, (char*)smAlo, tile_off8(arow + 16 * s, ac4 * 4), ra[s]);
#pragma unroll
        for (int s = 0; s < 8; s++)
            split_store((char*)smBhi, (char*)smBlo, tile_off8(arow + 16 * s, ac4 * 4), rb[s]);
        __syncthreads();
        if (kt + 1 < tiles) {
            loadA(kBase + (kt + 1) * 64);
            loadB(kBase + (kt + 1) * 64);
        }
#pragma unroll
        for (int ka = 0; ka < 4; ka++) {
            uint32_t afh[2][4], afl[2][4], bfh[4][2], bfl[4][2];
#pragma unroll
            for (int ma = 0; ma < 2; ma++) {
                int c = ka * 2 + aCbit;
                uint32_t off = aAtom[ma] + c * 128 + ((aLowr[ma] ^ c) << 4);
                asm volatile("ldmatrix.sync.aligned.m8n8.x4.shared.b16 {%0,%1,%2,%3}, [%4];"
                             : "=r"(afh[ma][0]), "=r"(afh[ma][1]), "=r"(afh[ma][2]), "=r"(afh[ma][3])
                             : "r"(aHi + off));
                asm volatile("ldmatrix.sync.aligned.m8n8.x4.shared.b16 {%0,%1,%2,%3}, [%4];"
                             : "=r"(afl[ma][0]), "=r"(afl[ma][1]), "=r"(afl[ma][2]), "=r"(afl[ma][3])
                             : "r"(aLo + off));
            }
#pragma unroll
            for (int na = 0; na < 4; na++) {
                int c = ka * 2 + bCbit;
                uint32_t off = bAtom[na] + c * 128 + ((bLowr[na] ^ c) << 4);
                asm volatile("ldmatrix.sync.aligned.m8n8.x2.shared.b16 {%0,%1}, [%2];"
                             : "=r"(bfh[na][0]), "=r"(bfh[na][1]) : "r"(bHi + off));
                asm volatile("ldmatrix.sync.aligned.m8n8.x2.shared.b16 {%0,%1}, [%2];"
                             : "=r"(bfl[na][0]), "=r"(bfl[na][1]) : "r"(bLo + off));
            }
#pragma unroll
            for (int ma = 0; ma < 2; ma++)
#pragma unroll
                for (int na = 0; na < 4; na++) {
                    MMA_BF16(acc[ma][na], afh[ma], bfh[na][0], bfh[na][1]);
                    MMA_BF16(acc[ma][na], afh[ma], bfl[na][0], bfl[na][1]);
                    MMA_BF16(acc[ma][na], afl[ma], bfh[na][0], bfh[na][1]);
                }
        }
    }

    float* Cout = C + (size_t)blockIdx.y * 64 * N;
    int g = lane >> 2, tig = lane & 3;
#pragma unroll
    for (int ma = 0; ma < 2; ma++)
#pragma unroll
        for (int na = 0; na < 4; na++) {
            int col = nBase + wn * 32 + na * 8 + tig * 2;
            int r0 = wm * 32 + ma * 16 + g;
            *reinterpret_cast<float2*>(Cout + (size_t)r0 * N + col) =
                make_float2(acc[ma][na][0], acc[ma][na][1]);
            *reinterpret_cast<float2*>(Cout + (size_t)(r0 + 8) * N + col) =
                make_float2(acc[ma][na][2], acc[ma][na][3]);
        }
}

// ================= fat output GEMM: 2-MMA (A split, W rn) + bias + fused lsm =================
__global__ __launch_bounds__(256, 2) void k_outproj(const float* __restrict__ A,
                                                    const float* __restrict__ W,
                                                    const float* __restrict__ bias,
                                                    float* __restrict__ C,
                                                    float* __restrict__ pmax,
                                                    float* __restrict__ psum) {
    __shared__ __align__(16) uint32_t smAhi[2048], smAlo[2048];
    __shared__ __align__(16) uint32_t smB[4096];
    __shared__ float redMax[64][4];
    __shared__ float redSum[64][4];

    const int tid = threadIdx.x;
    const int lane = tid & 31, wid = tid >> 5;
    const int wm = wid & 1, wn = wid >> 1;
    const int nBase = blockIdx.x * 128;

    uint32_t aHi = (uint32_t)__cvta_generic_to_shared(smAhi);
    uint32_t aLo = (uint32_t)__cvta_generic_to_shared(smAlo);
    uint32_t bSm = (uint32_t)__cvta_generic_to_shared(smB);

    int aAtom[2], aLowr[2];
#pragma unroll
    for (int ma = 0; ma < 2; ma++) {
        int row = wm * 32 + ma * 16 + ((lane >> 3) & 1) * 8 + (lane & 7);
        aAtom[ma] = (row >> 3) << 10;
        aLowr[ma] = row & 7;
    }
    const int aCbit = lane >> 4;
    int bAtom[4], bLowr[4];
    const int ll = lane & 15;
#pragma unroll
    for (int na = 0; na < 4; na++) {
        int n = wn * 32 + na * 8 + (ll & 7);
        bAtom[na] = (n >> 3) << 10;
        bLowr[na] = n & 7;
    }
    const int bCbit = ll >> 3;

    float acc[2][4][4];
#pragma unroll
    for (int i = 0; i < 2; i++)
#pragma unroll
        for (int j = 0; j < 4; j++)
#pragma unroll
            for (int q = 0; q < 4; q++) acc[i][j][q] = 0.f;

    float4 ra[4], rb[8];
    const int arow = tid >> 4, ac4 = tid & 15;

    auto loadA = [&](int k0) {
#pragma unroll
        for (int s = 0; s < 4; s++)
            ra[s] = *reinterpret_cast<const float4*>(A + (size_t)(arow + 16 * s) * 1024 + k0 + ac4 * 4);
    };
    auto loadB = [&](int k0) {
#pragma unroll
        for (int s = 0; s < 8; s++) {
            int ng = nBase + arow + 16 * s;
            if (ng < VV)
                rb[s] = __ldcs(reinterpret_cast<const float4*>(W + (size_t)ng * 1024 + k0 + ac4 * 4));
            else
                rb[s] = make_float4(0.f, 0.f, 0.f, 0.f);
        }
    };

    loadA(0);
    loadB(0);

    for (int kt = 0; kt < 16; kt++) {
        __syncthreads();
#pragma unroll
        for (int s = 0; s < 4; s++)
            split_store((char*)smAhi, (char*)smAlo, tile_off8(arow + 16 * s, ac4 * 4), ra[s]);
#pragma unroll
        for (int s = 0; s < 8; s++)
            rn_store((char*)smB, tile_off8(arow + 16 * s, ac4 * 4), rb[s]);
        __syncthreads();
        if (kt + 1 < 16) {
            loadA((kt + 1) * 64);
            loadB((kt + 1) * 64);
        }
#pragma unroll
        for (int ka = 0; ka < 4; ka++) {
            uint32_t afh[2][4], afl[2][4], bf[4][2];
#pragma unroll
            for (int ma = 0; ma < 2; ma++) {
                int c = ka * 2 + aCbit;
                uint32_t off = aAtom[ma] + c * 128 + ((aLowr[ma] ^ c) << 4);
                asm volatile("ldmatrix.sync.aligned.m8n8.x4.shared.b16 {%0,%1,%2,%3}, [%4];"
                             : "=r"(afh[ma][0]), "=r"(afh[ma][1]), "=r"(afh[ma][2]), "=r"(afh[ma][3])
                             : "r"(aHi + off));
                asm volatile("ldmatrix.sync.aligned.m8n8.x4.shared.b16 {%0,%1,%2,%3}, [%4];"
                             : "=r"(afl[ma][0]), "=r"(afl[ma][1]), "=r"(afl[ma][2]), "=r"(afl[ma][3])
                             : "r"(aLo + off));
            }
#pragma unroll
            for (int na = 0; na < 4; na++) {
                int c = ka * 2 + bCbit;
                uint32_t off = bAtom[na] + c * 128 + ((bLowr[na] ^ c) << 4);
                asm volatile("ldmatrix.sync.aligned.m8n8.x2.shared.b16 {%0,%1}, [%2];"
                             : "=r"(bf[na][0]), "=r"(bf[na][1]) : "r"(bSm + off));
            }
#pragma unroll
            for (int ma = 0; ma < 2; ma++)
#pragma unroll
                for (int na = 0; na < 4; na++) {
                    MMA_BF16(acc[ma][na], afh[ma], bf[na][0], bf[na][1]);
                    MMA_BF16(acc[ma][na], afl[ma], bf[na][0], bf[na][1]);
                }
        }
    }

    int g = lane >> 2, tig = lane & 3;
#pragma unroll
    for (int ma = 0; ma < 2; ma++)
#pragma unroll
        for (int na = 0; na < 4; na++) {
            int col = nBase + wn * 32 + na * 8 + tig * 2;
            int r0 = wm * 32 + ma * 16 + g;
            if (col < VV) {
                float b0 = bias[col];
                acc[ma][na][0] += b0; acc[ma][na][2] += b0;
                C[(size_t)r0 * VV + col]       = acc[ma][na][0];
                C[(size_t)(r0 + 8) * VV + col] = acc[ma][na][2];
            } else { acc[ma][na][0] = -1e30f; acc[ma][na][2] = -1e30f; }
            if (col + 1 < VV) {
                float b1 = bias[col + 1];
                acc[ma][na][1] += b1; acc[ma][na][3] += b1;
                C[(size_t)r0 * VV + col + 1]       = acc[ma][na][1];
                C[(size_t)(r0 + 8) * VV + col + 1] = acc[ma][na][3];
            } else { acc[ma][na][1] = -1e30f; acc[ma][na][3] = -1e30f; }
        }

#pragma unroll
    for (int ma = 0; ma < 2; ma++) {
        float m0 = -1e30f, m1 = -1e30f;
#pragma unroll
        for (int na = 0; na < 4; na++) {
            m0 = fmaxf(m0, fmaxf(acc[ma][na][0], acc[ma][na][1]));
            m1 = fmaxf(m1, fmaxf(acc[ma][na][2], acc[ma][na][3]));
        }
        m0 = fmaxf(m0, __shfl_xor_sync(~0u, m0, 1));
        m0 = fmaxf(m0, __shfl_xor_sync(~0u, m0, 2));
        m1 = fmaxf(m1, __shfl_xor_sync(~0u, m1, 1));
        m1 = fmaxf(m1, __shfl_xor_sync(~0u, m1, 2));
        if (tig == 0) {
            redMax[wm * 32 + ma * 16 + g][wn] = m0;
            redMax[wm * 32 + ma * 16 + g + 8][wn] = m1;
        }
    }
    __syncthreads();
#pragma unroll
    for (int ma = 0; ma < 2; ma++)
#pragma unroll
        for (int h = 0; h < 2; h++) {
            int row = wm * 32 + ma * 16 + g + h * 8;
            float rm = fmaxf(fmaxf(redMax[row][0], redMax[row][1]),
                             fmaxf(redMax[row][2], redMax[row][3]));
            float s = 0.f;
#pragma unroll
            for (int na = 0; na < 4; na++) {
                s += __expf(acc[ma][na][h * 2] - rm);
                s += __expf(acc[ma][na][h * 2 + 1] - rm);
            }
            s += __shfl_xor_sync(~0u, s, 1);
            s += __shfl_xor_sync(~0u, s, 2);
            if (tig == 0) redSum[row][wn] = s;
        }
    __syncthreads();
    if (tid < 64) {
        float rm = fmaxf(fmaxf(redMax[tid][0], redMax[tid][1]),
                         fmaxf(redMax[tid][2], redMax[tid][3]));
        float s = redSum[tid][0] + redSum[tid][1] + redSum[tid][2] + redSum[tid][3];
        pmax[tid * 512 + blockIdx.x] = rm;
        psum[tid * 512 + blockIdx.x] = s;
    }
}

// ================= fused attention context: softmax + weighted sum over enc =================
__global__ __launch_bounds__(256) void k_attnctx(const float* __restrict__ part,
                                                 const float* __restrict__ bias,
                                                 const float* __restrict__ enc,
                                                 float4* __restrict__ out) {
    const int tid = threadIdx.x;
    const int b = blockIdx.y;
    __shared__ float ws[512];
    __shared__ float red[8];
    __shared__ float4 racc[8][32];

    float v0 = bias[tid], v1 = bias[tid + 256];
#pragma unroll
    for (int s = 0; s < 16; s++) {
        size_t base = ((size_t)s * BB + b) * LL;
        v0 += part[base + tid];
        v1 += part[base + tid + 256];
    }
    float m = fmaxf(v0, v1);
#pragma unroll
    for (int o = 16; o > 0; o >>= 1) m = fmaxf(m, __shfl_xor_sync(~0u, m, o));
    if ((tid & 31) == 0) red[tid >> 5] = m;
    __syncthreads();
    if (tid == 0) {
        float t = red[0];
#pragma unroll
        for (int i = 1; i < 8; i++) t = fmaxf(t, red[i]);
        red[0] = t;
    }
    __syncthreads();
    float M = red[0];
    __syncthreads();
    float e0 = __expf(v0 - M), e1 = __expf(v1 - M);
    float ss = e0 + e1;
#pragma unroll
    for (int o = 16; o > 0; o >>= 1) ss += __shfl_xor_sync(~0u, ss, o);
    if ((tid & 31) == 0) red[tid >> 5] = ss;
    __syncthreads();
    if (tid == 0) {
        float t = 0.f;
#pragma unroll
        for (int i = 0; i < 8; i++) t += red[i];
        red[0] = t;
    }
    __syncthreads();
    float S = red[0];
    ws[tid] = e0 / S;
    ws[tid + 256] = e1 / S;
    __syncthreads();

    const int c = tid & 31;
    const int g = tid >> 5;
    const float4* ep = reinterpret_cast<const float4*>(enc + (size_t)b * LL * HH)
                       + blockIdx.x * 32 + c;
    float4 acc = make_float4(0.f, 0.f, 0.f, 0.f);
    int l0 = g * 64;
#pragma unroll 8
    for (int l = l0; l < l0 + 64; l++) {
        float4 v = __ldcs(ep + (size_t)l * (HH / 4));
        float w = ws[l];
        acc.x += w * v.x; acc.y += w * v.y; acc.z += w * v.z; acc.w += w * v.w;
    }
    racc[g][c] = acc;
    __syncthreads();
    if (tid < 32) {
        float4 r = racc[0][tid];
#pragma unroll
        for (int i = 1; i < 8; i++) {
            float4 p = racc[i][tid];
            r.x += p.x; r.y += p.y; r.z += p.z; r.w += p.w;
        }
        out[(size_t)b * (HH / 4) + blockIdx.x * 32 + tid] = r;
    }
}

// ---------------- combine reduce + bias + relu (float4, 8 splits) ----------------
__global__ void k_combrelu(const float4* __restrict__ part, const float4* __restrict__ bias,
                           float4* __restrict__ out) {
    int idx = blockIdx.x * 256 + threadIdx.x;   // 16384
    float4 b = bias[idx & 255];
    float4 v = b;
#pragma unroll
    for (int s = 0; s < 8; s++) {
        float4 p = __ldcs(part + (size_t)s * 16384 + idx);
        v.x += p.x; v.y += p.y; v.z += p.z; v.w += p.w;
    }
    out[idx] = make_float4(fmaxf(v.x, 0.f), fmaxf(v.y, 0.f), fmaxf(v.z, 0.f), fmaxf(v.w, 0.f));
}

// ---------------- GRU gates (float4, split 4) ----------------
__global__ void k_gru(const float4* __restrict__ pgi, const float4* __restrict__ pgh,
                      const float4* __restrict__ bih, const float4* __restrict__ bhh,
                      const float4* __restrict__ hidden, float4* __restrict__ newh) {
    int idx = blockIdx.x * 256 + threadIdx.x;   // 16384
    int b = idx >> 8;
    int h4 = idx & 255;
    float4 ir = bih[h4], iz = bih[256 + h4], in_ = bih[512 + h4];
    float4 hr = bhh[h4], hz = bhh[256 + h4], hn = bhh[512 + h4];
#pragma unroll
    for (int s = 0; s < 4; s++) {
        size_t base = (size_t)(s * BB + b) * 768;
        float4 p;
        p = __ldcs(pgi + base + h4);        ir.x += p.x; ir.y += p.y; ir.z += p.z; ir.w += p.w;
        p = __ldcs(pgi + base + 256 + h4);  iz.x += p.x; iz.y += p.y; iz.z += p.z; iz.w += p.w;
        p = __ldcs(pgi + base + 512 + h4);  in_.x += p.x; in_.y += p.y; in_.z += p.z; in_.w += p.w;
        p = __ldcs(pgh + base + h4);        hr.x += p.x; hr.y += p.y; hr.z += p.z; hr.w += p.w;
        p = __ldcs(pgh + base + 256 + h4);  hz.x += p.x; hz.y += p.y; hz.z += p.z; hz.w += p.w;
        p = __ldcs(pgh + base + 512 + h4);  hn.x += p.x; hn.y += p.y; hn.z += p.z; hn.w += p.w;
    }
    float4 hd = hidden[idx];
    float4 o;
    {
        float r = 1.f / (1.f + expf(-(ir.x + hr.x)));
        float z = 1.f / (1.f + expf(-(iz.x + hz.x)));
        float n = tanhf(in_.x + r * hn.x);
        o.x = (1.f - z) * n + z * hd.x;
    }
    {
        float r = 1.f / (1.f + expf(-(ir.y + hr.y)));
        float z = 1.f / (1.f + expf(-(iz.y + hz.y)));
        float n = tanhf(in_.y + r * hn.y);
        o.y = (1.f - z) * n + z * hd.y;
    }
    {
        float r = 1.f / (1.f + expf(-(ir.z + hr.z)));
        float z = 1.f / (1.f + expf(-(iz.z + hz.z)));
        float n = tanhf(in_.z + r * hn.z);
        o.z = (1.f - z) * n + z * hd.z;
    }
    {
        float r = 1.f / (1.f + expf(-(ir.w + hr.w)));
        float z = 1.f / (1.f + expf(-(iz.w + hz.w)));
        float n = tanhf(in_.w + r * hn.w);
        o.w = (1.f - z) * n + z * hd.w;
    }
    newh[idx] = o;
}

// ---------------- fused lsm: each block computes its row's lse, then subtracts ----------------
__global__ void k_lsm_write(float* __restrict__ out,
                            const float* __restrict__ pmax, const float* __restrict__ psum) {
    int c = blockIdx.x;          // 8 chunks
    int b = blockIdx.y;
    __shared__ float red[8];
    __shared__ float s_lse;

    float m = -1e30f;
    for (int i = threadIdx.x; i < NBLK_OUT; i += 256) m = fmaxf(m, pmax[b * 512 + i]);
#pragma unroll
    for (int o = 16; o > 0; o >>= 1) m = fmaxf(m, __shfl_xor_sync(~0u, m, o));
    if ((threadIdx.x & 31) == 0) red[threadIdx.x >> 5] = m;
    __syncthreads();
    if (threadIdx.x == 0) {
        float t = red[0];
#pragma unroll
        for (int i = 1; i < 8; i++) t = fmaxf(t, red[i]);
        red[0] = t;
    }
    __syncthreads();
    float M = red[0];
    __syncthreads();
    float s = 0.f;
    for (int i = threadIdx.x; i < NBLK_OUT; i += 256)
        s += psum[b * 512 + i] * __expf(pmax[b * 512 + i] - M);
#pragma unroll
    for (int o = 16; o > 0; o >>= 1) s += __shfl_xor_sync(~0u, s, o);
    if ((threadIdx.x & 31) == 0) red[threadIdx.x >> 5] = s;
    __syncthreads();
    if (threadIdx.x == 0) {
        float t = 0.f;
#pragma unroll
        for (int i = 0; i < 8; i++) t += red[i];
        s_lse = M + logf(t);
    }
    __syncthreads();
    float L = s_lse;

    const int CH = (VV + 7) / 8;
    int start = c * CH;
    int end = min(start + CH, VV);
    float* row = out + (size_t)b * VV;
    for (int i = start + threadIdx.x; i < end; i += 256) row[i] -= L;
}

// ---------------- launch ----------------
extern "C" void kernel_launch(void* const* d_in, const int* in_sizes, int n_in,
                              void* d_out, int out_size) {
    const int*   ids    = (const int*)  d_in[0];
    const float* hidden = (const float*)d_in[1];
    const float* enc    = (const float*)d_in[2];
    const float* embW   = (const float*)d_in[3];
    const float* attnW  = (const float*)d_in[4];
    const float* attnb  = (const float*)d_in[5];
    const float* combW  = (const float*)d_in[6];
    const float* combb  = (const float*)d_in[7];
    const float* Wih    = (const float*)d_in[8];
    const float* Whh    = (const float*)d_in[9];
    const float* bih    = (const float*)d_in[10];
    const float* bhh    = (const float*)d_in[11];
    const float* outW   = (const float*)d_in[12];
    const float* outb   = (const float*)d_in[13];

    float* out  = (float*)d_out;
    float* newh = out + (size_t)BB * VV;

    float *p_attnapp, *p_x, *p_pa, *p_gh, *p_pmax, *p_psum;
    cudaGetSymbolAddress((void**)&p_attnapp, g_attnapp);
    cudaGetSymbolAddress((void**)&p_x, g_x);
    cudaGetSymbolAddress((void**)&p_pa, g_partA);
    cudaGetSymbolAddress((void**)&p_gh, g_partB);
    cudaGetSymbolAddress((void**)&p_pmax, g_pmax);
    cudaGetSymbolAddress((void**)&p_psum, g_psum);

    // 1. merged launch: z=0 attn logits GEMM (4x16, split-K 16); z=1 gh GEMM (24x4, split-K 4)
    gemm_bf16s<<<dim3(24, 16, 2), 256>>>(embW, hidden, ids, EE, EE + HH, attnW,
                                         p_pa, LL, 128, 4, 16,
                                         hidden, Whh, p_gh, 3 * HH, 256, HH, 24, 4);

    // 2. fused softmax + attention context
    k_attnctx<<<dim3(8, BB), 256>>>(p_pa, attnb, enc, (float4*)p_attnapp);

    // 3. combine: cat(gather(emb), attn_applied) @ comb_W^T, split-K 8
    gemm_bf16s<<<dim3(8, 8, 1), 256>>>(embW, p_attnapp, ids, EE, EE + HH, combW,
                                       p_pa, EE, 256, 8, 8,
                                       nullptr, nullptr, nullptr, 0, 64, 0, 0, 0);
    k_combrelu<<<64, 256>>>((const float4*)p_pa, (const float4*)combb, (float4*)p_x);

    // 4. GRU gi = x @ Wih^T, split-K 4
    gemm_bf16s<<<dim3(24, 4, 1), 256>>>(p_x, nullptr, nullptr, HH, HH, Wih,
                                        p_pa, 3 * HH, 256, 24, 4,
                                        nullptr, nullptr, nullptr, 0, 64, 0, 0, 0);
    k_gru<<<64, 256>>>((const float4*)p_pa, (const float4*)p_gh,
                       (const float4*)bih, (const float4*)bhh,
                       (const float4*)hidden, (float4*)newh);

    // 5. output projection (2-MMA split-A bf16, 2 blocks/SM) + fused lsm partials
    k_outproj<<<NBLK_OUT, 256>>>(newh, outW, outb, out, p_pmax, p_psum);

    // 6. fused lse + subtract
    k_lsm_write<<<dim3(8, BB), 256>>>(out, p_pmax, p_psum);
}

// round 15
// speedup vs baseline: 1.0166x; 1.0166x over previous
#include <cuda_runtime.h>
#include <math.h>
#include <stdint.h>

#define BB 64
#define EE 1024
#define HH 1024
#define LL 512
#define VV 50257
#define NBLK_OUT 393   // ceil(VV/128)

// ---------------- scratch (device globals, no allocation) ----------------
__device__ float g_attnapp[BB * HH];
__device__ float g_x[BB * EE];
__device__ float g_partA[16 * BB * EE];      // attn 8*64*512=262K, comb 8*64*1024=524K, gi 4*64*3072=786K (cap 1.05M)
__device__ float g_partB[12 * BB * EE];      // gh 4*64*3072 = 786,432 floats (cap exact)
__device__ float g_pmax[64 * 512];
__device__ float g_psum[64 * 512];

// ---------------- helpers ----------------
__device__ __forceinline__ uint32_t pack_bf16(float lo, float hi) {
    uint32_t r;
    asm("cvt.rn.bf16x2.f32 %0, %1, %2;" : "=r"(r) : "f"(hi), "f"(lo));
    return r;
}
__device__ __forceinline__ int tile_off8(int row, int k) {
    int c = k >> 3;
    return (((row >> 3) << 3) + c) * 128 + (((row & 7) ^ c) << 4) + (k & 7) * 2;
}
__device__ __forceinline__ void split_store(char* hiP, char* loP, int off, float4 v) {
    uint32_t bx = __float_as_uint(v.x), by = __float_as_uint(v.y);
    uint32_t bz = __float_as_uint(v.z), bw = __float_as_uint(v.w);
    uint2 hi = make_uint2(__byte_perm(bx, by, 0x7632), __byte_perm(bz, bw, 0x7632));
    float lx = v.x - __uint_as_float(bx & 0xffff0000u);
    float ly = v.y - __uint_as_float(by & 0xffff0000u);
    float lz = v.z - __uint_as_float(bz & 0xffff0000u);
    float lw = v.w - __uint_as_float(bw & 0xffff0000u);
    uint2 lo = make_uint2(pack_bf16(lx, ly), pack_bf16(lz, lw));
    *reinterpret_cast<uint2*>(hiP + off) = hi;
    *reinterpret_cast<uint2*>(loP + off) = lo;
}
__device__ __forceinline__ void rn_store(char* P, int off, float4 v) {
    uint2 r = make_uint2(pack_bf16(v.x, v.y), pack_bf16(v.z, v.w));
    *reinterpret_cast<uint2*>(P + off) = r;
}

#define MMA_BF16(ac, a, b0, b1)                                                   \
    asm volatile("mma.sync.aligned.m16n8k16.row.col.f32.bf16.bf16.f32 "           \
                 "{%0,%1,%2,%3}, {%4,%5,%6,%7}, {%8,%9}, {%0,%1,%2,%3};"          \
                 : "+f"((ac)[0]), "+f"((ac)[1]), "+f"((ac)[2]), "+f"((ac)[3])     \
                 : "r"((a)[0]), "r"((a)[1]), "r"((a)[2]), "r"((a)[3]),            \
                   "r"(b0), "r"(b1))

// ================= split-bf16 tensor GEMM (split-K partials, 3-MMA) =================
__global__ __launch_bounds__(256) void gemm_bf16s(
    const float* A1, const float* A2, const int* gids, int K1, int K,
    const float* W, float* C, int N, int kChunk, int gx, int gy,
    const float* A1b, const float* Wb, float* Cb, int Nb, int kChunkB, int Kb, int gxB, int gyB) {
    if (blockIdx.z == 1) {
        if ((int)blockIdx.x >= gxB || (int)blockIdx.y >= gyB) return;
        A1 = A1b; A2 = nullptr; gids = nullptr; K1 = Kb; K = Kb;
        W = Wb; C = Cb; N = Nb; kChunk = kChunkB;
    } else {
        if ((int)blockIdx.x >= gx || (int)blockIdx.y >= gy) return;
    }

    __shared__ __align__(16) uint32_t smAhi[2048], smAlo[2048];
    __shared__ __align__(16) uint32_t smBhi[4096], smBlo[4096];

    const int tid = threadIdx.x;
    const int lane = tid & 31, wid = tid >> 5;
    const int wm = wid & 1, wn = wid >> 1;
    const int nBase = blockIdx.x * 128;
    const int kBase = blockIdx.y * kChunk;
    const int tiles = kChunk >> 6;

    uint32_t aHi = (uint32_t)__cvta_generic_to_shared(smAhi);
    uint32_t aLo = (uint32_t)__cvta_generic_to_shared(smAlo);
    uint32_t bHi = (uint32_t)__cvta_generic_to_shared(smBhi);
    uint32_t bLo = (uint32_t)__cvta_generic_to_shared(smBlo);

    int aAtom[2], aLowr[2];
#pragma unroll
    for (int ma = 0; ma < 2; ma++) {
        int row = wm * 32 + ma * 16 + ((lane >> 3) & 1) * 8 + (lane & 7);
        aAtom[ma] = (row >> 3) << 10;
        aLowr[ma] = row & 7;
    }
    const int aCbit = lane >> 4;
    int bAtom[4], bLowr[4];
    const int ll = lane & 15;
#pragma unroll
    for (int na = 0; na < 4; na++) {
        int n = wn * 32 + na * 8 + (ll & 7);
        bAtom[na] = (n >> 3) << 10;
        bLowr[na] = n & 7;
    }
    const int bCbit = ll >> 3;

    float acc[2][4][4];
#pragma unroll
    for (int i = 0; i < 2; i++)
#pragma unroll
        for (int j = 0; j < 4; j++)
#pragma unroll
            for (int q = 0; q < 4; q++) acc[i][j][q] = 0.f;

    float4 ra[4], rb[8];
    const int arow = tid >> 4, ac4 = tid & 15;

    auto loadA = [&](int k0) {
#pragma unroll
        for (int s = 0; s < 4; s++) {
            int row = arow + 16 * s;
            int k = k0 + ac4 * 4;
            const float* rp;
            if (k < K1) rp = (gids ? A1 + (size_t)gids[row] * K1 : A1 + (size_t)row * K1) + k;
            else        rp = A2 + (size_t)row * (K - K1) + (k - K1);
            ra[s] = *reinterpret_cast<const float4*>(rp);
        }
    };
    auto loadB = [&](int k0) {
#pragma unroll
        for (int s = 0; s < 8; s++)
            rb[s] = __ldcs(reinterpret_cast<const float4*>(
                W + (size_t)(nBase + arow + 16 * s) * K + k0 + ac4 * 4));
    };

    loadA(kBase);
    loadB(kBase);

    for (int kt = 0; kt < tiles; kt++) {
        __syncthreads();
#pragma unroll
        for (int s = 0; s < 4; s++)
            split_store((char*)smAhi, (char*)smAlo, tile_off8(arow + 16 * s, ac4 * 4), ra[s]);
#pragma unroll
        for (int s = 0; s < 8; s++)
            split_store((char*)smBhi, (char*)smBlo, tile_off8(arow + 16 * s, ac4 * 4), rb[s]);
        __syncthreads();
        if (kt + 1 < tiles) {
            loadA(kBase + (kt + 1) * 64);
            loadB(kBase + (kt + 1) * 64);
        }
#pragma unroll
        for (int ka = 0; ka < 4; ka++) {
            uint32_t afh[2][4], afl[2][4], bfh[4][2], bfl[4][2];
#pragma unroll
            for (int ma = 0; ma < 2; ma++) {
                int c = ka * 2 + aCbit;
                uint32_t off = aAtom[ma] + c * 128 + ((aLowr[ma] ^ c) << 4);
                asm volatile("ldmatrix.sync.aligned.m8n8.x4.shared.b16 {%0,%1,%2,%3}, [%4];"
                             : "=r"(afh[ma][0]), "=r"(afh[ma][1]), "=r"(afh[ma][2]), "=r"(afh[ma][3])
                             : "r"(aHi + off));
                asm volatile("ldmatrix.sync.aligned.m8n8.x4.shared.b16 {%0,%1,%2,%3}, [%4];"
                             : "=r"(afl[ma][0]), "=r"(afl[ma][1]), "=r"(afl[ma][2]), "=r"(afl[ma][3])
                             : "r"(aLo + off));
            }
#pragma unroll
            for (int na = 0; na < 4; na++) {
                int c = ka * 2 + bCbit;
                uint32_t off = bAtom[na] + c * 128 + ((bLowr[na] ^ c) << 4);
                asm volatile("ldmatrix.sync.aligned.m8n8.x2.shared.b16 {%0,%1}, [%2];"
                             : "=r"(bfh[na][0]), "=r"(bfh[na][1]) : "r"(bHi + off));
                asm volatile("ldmatrix.sync.aligned.m8n8.x2.shared.b16 {%0,%1}, [%2];"
                             : "=r"(bfl[na][0]), "=r"(bfl[na][1]) : "r"(bLo + off));
            }
#pragma unroll
            for (int ma = 0; ma < 2; ma++)
#pragma unroll
                for (int na = 0; na < 4; na++) {
                    MMA_BF16(acc[ma][na], afh[ma], bfh[na][0], bfh[na][1]);
                    MMA_BF16(acc[ma][na], afh[ma], bfl[na][0], bfl[na][1]);
                    MMA_BF16(acc[ma][na], afl[ma], bfh[na][0], bfh[na][1]);
                }
        }
    }

    float* Cout = C + (size_t)blockIdx.y * 64 * N;
    int g = lane >> 2, tig = lane & 3;
#pragma unroll
    for (int ma = 0; ma < 2; ma++)
#pragma unroll
        for (int na = 0; na < 4; na++) {
            int col = nBase + wn * 32 + na * 8 + tig * 2;
            int r0 = wm * 32 + ma * 16 + g;
            *reinterpret_cast<float2*>(Cout + (size_t)r0 * N + col) =
                make_float2(acc[ma][na][0], acc[ma][na][1]);
            *reinterpret_cast<float2*>(Cout + (size_t)(r0 + 8) * N + col) =
                make_float2(acc[ma][na][2], acc[ma][na][3]);
        }
}

// ================= fat output GEMM: 2-MMA (A split, W rn) + bias + fused lsm =================
__global__ __launch_bounds__(256, 2) void k_outproj(const float* __restrict__ A,
                                                    const float* __restrict__ W,
                                                    const float* __restrict__ bias,
                                                    float* __restrict__ C,
                                                    float* __restrict__ pmax,
                                                    float* __restrict__ psum) {
    __shared__ __align__(16) uint32_t smAhi[2048], smAlo[2048];
    __shared__ __align__(16) uint32_t smB[4096];
    __shared__ float redMax[64][4];
    __shared__ float redSum[64][4];

    const int tid = threadIdx.x;
    const int lane = tid & 31, wid = tid >> 5;
    const int wm = wid & 1, wn = wid >> 1;
    const int nBase = blockIdx.x * 128;

    uint32_t aHi = (uint32_t)__cvta_generic_to_shared(smAhi);
    uint32_t aLo = (uint32_t)__cvta_generic_to_shared(smAlo);
    uint32_t bSm = (uint32_t)__cvta_generic_to_shared(smB);

    int aAtom[2], aLowr[2];
#pragma unroll
    for (int ma = 0; ma < 2; ma++) {
        int row = wm * 32 + ma * 16 + ((lane >> 3) & 1) * 8 + (lane & 7);
        aAtom[ma] = (row >> 3) << 10;
        aLowr[ma] = row & 7;
    }
    const int aCbit = lane >> 4;
    int bAtom[4], bLowr[4];
    const int ll = lane & 15;
#pragma unroll
    for (int na = 0; na < 4; na++) {
        int n = wn * 32 + na * 8 + (ll & 7);
        bAtom[na] = (n >> 3) << 10;
        bLowr[na] = n & 7;
    }
    const int bCbit = ll >> 3;

    float acc[2][4][4];
#pragma unroll
    for (int i = 0; i < 2; i++)
#pragma unroll
        for (int j = 0; j < 4; j++)
#pragma unroll
            for (int q = 0; q < 4; q++) acc[i][j][q] = 0.f;

    float4 ra[4], rb[8];
    const int arow = tid >> 4, ac4 = tid & 15;

    auto loadA = [&](int k0) {
#pragma unroll
        for (int s = 0; s < 4; s++)
            ra[s] = *reinterpret_cast<const float4*>(A + (size_t)(arow + 16 * s) * 1024 + k0 + ac4 * 4);
    };
    auto loadB = [&](int k0) {
#pragma unroll
        for (int s = 0; s < 8; s++) {
            int ng = nBase + arow + 16 * s;
            if (ng < VV)
                rb[s] = __ldcs(reinterpret_cast<const float4*>(W + (size_t)ng * 1024 + k0 + ac4 * 4));
            else
                rb[s] = make_float4(0.f, 0.f, 0.f, 0.f);
        }
    };

    loadA(0);
    loadB(0);

    for (int kt = 0; kt < 16; kt++) {
        __syncthreads();
#pragma unroll
        for (int s = 0; s < 4; s++)
            split_store((char*)smAhi, (char*)smAlo, tile_off8(arow + 16 * s, ac4 * 4), ra[s]);
#pragma unroll
        for (int s = 0; s < 8; s++)
            rn_store((char*)smB, tile_off8(arow + 16 * s, ac4 * 4), rb[s]);
        __syncthreads();
        if (kt + 1 < 16) {
            loadA((kt + 1) * 64);
            loadB((kt + 1) * 64);
        }
#pragma unroll
        for (int ka = 0; ka < 4; ka++) {
            uint32_t afh[2][4], afl[2][4], bf[4][2];
#pragma unroll
            for (int ma = 0; ma < 2; ma++) {
                int c = ka * 2 + aCbit;
                uint32_t off = aAtom[ma] + c * 128 + ((aLowr[ma] ^ c) << 4);
                asm volatile("ldmatrix.sync.aligned.m8n8.x4.shared.b16 {%0,%1,%2,%3}, [%4];"
                             : "=r"(afh[ma][0]), "=r"(afh[ma][1]), "=r"(afh[ma][2]), "=r"(afh[ma][3])
                             : "r"(aHi + off));
                asm volatile("ldmatrix.sync.aligned.m8n8.x4.shared.b16 {%0,%1,%2,%3}, [%4];"
                             : "=r"(afl[ma][0]), "=r"(afl[ma][1]), "=r"(afl[ma][2]), "=r"(afl[ma][3])
                             : "r"(aLo + off));
            }
#pragma unroll
            for (int na = 0; na < 4; na++) {
                int c = ka * 2 + bCbit;
                uint32_t off = bAtom[na] + c * 128 + ((bLowr[na] ^ c) << 4);
                asm volatile("ldmatrix.sync.aligned.m8n8.x2.shared.b16 {%0,%1}, [%2];"
                             : "=r"(bf[na][0]), "=r"(bf[na][1]) : "r"(bSm + off));
            }
#pragma unroll
            for (int ma = 0; ma < 2; ma++)
#pragma unroll
                for (int na = 0; na < 4; na++) {
                    MMA_BF16(acc[ma][na], afh[ma], bf[na][0], bf[na][1]);
                    MMA_BF16(acc[ma][na], afl[ma], bf[na][0], bf[na][1]);
                }
        }
    }

    int g = lane >> 2, tig = lane & 3;
#pragma unroll
    for (int ma = 0; ma < 2; ma++)
#pragma unroll
        for (int na = 0; na < 4; na++) {
            int col = nBase + wn * 32 + na * 8 + tig * 2;
            int r0 = wm * 32 + ma * 16 + g;
            if (col < VV) {
                float b0 = bias[col];
                acc[ma][na][0] += b0; acc[ma][na][2] += b0;
                C[(size_t)r0 * VV + col]       = acc[ma][na][0];
                C[(size_t)(r0 + 8) * VV + col] = acc[ma][na][2];
            } else { acc[ma][na][0] = -1e30f; acc[ma][na][2] = -1e30f; }
            if (col + 1 < VV) {
                float b1 = bias[col + 1];
                acc[ma][na][1] += b1; acc[ma][na][3] += b1;
                C[(size_t)r0 * VV + col + 1]       = acc[ma][na][1];
                C[(size_t)(r0 + 8) * VV + col + 1] = acc[ma][na][3];
            } else { acc[ma][na][1] = -1e30f; acc[ma][na][3] = -1e30f; }
        }

#pragma unroll
    for (int ma = 0; ma < 2; ma++) {
        float m0 = -1e30f, m1 = -1e30f;
#pragma unroll
        for (int na = 0; na < 4; na++) {
            m0 = fmaxf(m0, fmaxf(acc[ma][na][0], acc[ma][na][1]));
            m1 = fmaxf(m1, fmaxf(acc[ma][na][2], acc[ma][na][3]));
        }
        m0 = fmaxf(m0, __shfl_xor_sync(~0u, m0, 1));
        m0 = fmaxf(m0, __shfl_xor_sync(~0u, m0, 2));
        m1 = fmaxf(m1, __shfl_xor_sync(~0u, m1, 1));
        m1 = fmaxf(m1, __shfl_xor_sync(~0u, m1, 2));
        if (tig == 0) {
            redMax[wm * 32 + ma * 16 + g][wn] = m0;
            redMax[wm * 32 + ma * 16 + g + 8][wn] = m1;
        }
    }
    __syncthreads();
#pragma unroll
    for (int ma = 0; ma < 2; ma++)
#pragma unroll
        for (int h = 0; h < 2; h++) {
            int row = wm * 32 + ma * 16 + g + h * 8;
            float rm = fmaxf(fmaxf(redMax[row][0], redMax[row][1]),
                             fmaxf(redMax[row][2], redMax[row][3]));
            float s = 0.f;
#pragma unroll
            for (int na = 0; na < 4; na++) {
                s += __expf(acc[ma][na][h * 2] - rm);
                s += __expf(acc[ma][na][h * 2 + 1] - rm);
            }
            s += __shfl_xor_sync(~0u, s, 1);
            s += __shfl_xor_sync(~0u, s, 2);
            if (tig == 0) redSum[row][wn] = s;
        }
    __syncthreads();
    if (tid < 64) {
        float rm = fmaxf(fmaxf(redMax[tid][0], redMax[tid][1]),
                         fmaxf(redMax[tid][2], redMax[tid][3]));
        float s = redSum[tid][0] + redSum[tid][1] + redSum[tid][2] + redSum[tid][3];
        pmax[tid * 512 + blockIdx.x] = rm;
        psum[tid * 512 + blockIdx.x] = s;
    }
}

// ================= fused attention context: softmax + weighted sum over enc =================
__global__ __launch_bounds__(256) void k_attnctx(const float* __restrict__ part,
                                                 const float* __restrict__ bias,
                                                 const float* __restrict__ enc,
                                                 float4* __restrict__ out) {
    const int tid = threadIdx.x;
    const int b = blockIdx.y;
    __shared__ float ws[512];
    __shared__ float red[8];
    __shared__ float4 racc[8][32];

    float v0 = bias[tid], v1 = bias[tid + 256];
#pragma unroll
    for (int s = 0; s < 8; s++) {
        size_t base = ((size_t)s * BB + b) * LL;
        v0 += part[base + tid];
        v1 += part[base + tid + 256];
    }
    float m = fmaxf(v0, v1);
#pragma unroll
    for (int o = 16; o > 0; o >>= 1) m = fmaxf(m, __shfl_xor_sync(~0u, m, o));
    if ((tid & 31) == 0) red[tid >> 5] = m;
    __syncthreads();
    if (tid == 0) {
        float t = red[0];
#pragma unroll
        for (int i = 1; i < 8; i++) t = fmaxf(t, red[i]);
        red[0] = t;
    }
    __syncthreads();
    float M = red[0];
    __syncthreads();
    float e0 = __expf(v0 - M), e1 = __expf(v1 - M);
    float ss = e0 + e1;
#pragma unroll
    for (int o = 16; o > 0; o >>= 1) ss += __shfl_xor_sync(~0u, ss, o);
    if ((tid & 31) == 0) red[tid >> 5] = ss;
    __syncthreads();
    if (tid == 0) {
        float t = 0.f;
#pragma unroll
        for (int i = 0; i < 8; i++) t += red[i];
        red[0] = t;
    }
    __syncthreads();
    float S = red[0];
    ws[tid] = e0 / S;
    ws[tid + 256] = e1 / S;
    __syncthreads();

    const int c = tid & 31;
    const int g = tid >> 5;
    const float4* ep = reinterpret_cast<const float4*>(enc + (size_t)b * LL * HH)
                       + blockIdx.x * 32 + c;
    float4 acc = make_float4(0.f, 0.f, 0.f, 0.f);
    int l0 = g * 64;
#pragma unroll 8
    for (int l = l0; l < l0 + 64; l++) {
        float4 v = __ldcs(ep + (size_t)l * (HH / 4));
        float w = ws[l];
        acc.x += w * v.x; acc.y += w * v.y; acc.z += w * v.z; acc.w += w * v.w;
    }
    racc[g][c] = acc;
    __syncthreads();
    if (tid < 32) {
        float4 r = racc[0][tid];
#pragma unroll
        for (int i = 1; i < 8; i++) {
            float4 p = racc[i][tid];
            r.x += p.x; r.y += p.y; r.z += p.z; r.w += p.w;
        }
        out[(size_t)b * (HH / 4) + blockIdx.x * 32 + tid] = r;
    }
}

// ---------------- combine reduce + bias + relu (float4, 8 splits) ----------------
__global__ void k_combrelu(const float4* __restrict__ part, const float4* __restrict__ bias,
                           float4* __restrict__ out) {
    int idx = blockIdx.x * 256 + threadIdx.x;   // 16384
    float4 b = bias[idx & 255];
    float4 v = b;
#pragma unroll
    for (int s = 0; s < 8; s++) {
        float4 p = __ldcs(part + (size_t)s * 16384 + idx);
        v.x += p.x; v.y += p.y; v.z += p.z; v.w += p.w;
    }
    out[idx] = make_float4(fmaxf(v.x, 0.f), fmaxf(v.y, 0.f), fmaxf(v.z, 0.f), fmaxf(v.w, 0.f));
}

// ---------------- GRU gates (float4, split 4) ----------------
__global__ void k_gru(const float4* __restrict__ pgi, const float4* __restrict__ pgh,
                      const float4* __restrict__ bih, const float4* __restrict__ bhh,
                      const float4* __restrict__ hidden, float4* __restrict__ newh) {
    int idx = blockIdx.x * 256 + threadIdx.x;   // 16384
    int b = idx >> 8;
    int h4 = idx & 255;
    float4 ir = bih[h4], iz = bih[256 + h4], in_ = bih[512 + h4];
    float4 hr = bhh[h4], hz = bhh[256 + h4], hn = bhh[512 + h4];
#pragma unroll
    for (int s = 0; s < 4; s++) {
        size_t base = (size_t)(s * BB + b) * 768;
        float4 p;
        p = __ldcs(pgi + base + h4);        ir.x += p.x; ir.y += p.y; ir.z += p.z; ir.w += p.w;
        p = __ldcs(pgi + base + 256 + h4);  iz.x += p.x; iz.y += p.y; iz.z += p.z; iz.w += p.w;
        p = __ldcs(pgi + base + 512 + h4);  in_.x += p.x; in_.y += p.y; in_.z += p.z; in_.w += p.w;
        p = __ldcs(pgh + base + h4);        hr.x += p.x; hr.y += p.y; hr.z += p.z; hr.w += p.w;
        p = __ldcs(pgh + base + 256 + h4);  hz.x += p.x; hz.y += p.y; hz.z += p.z; hz.w += p.w;
        p = __ldcs(pgh + base + 512 + h4);  hn.x += p.x; hn.y += p.y; hn.z += p.z; hn.w += p.w;
    }
    float4 hd = hidden[idx];
    float4 o;
    {
        float r = 1.f / (1.f + expf(-(ir.x + hr.x)));
        float z = 1.f / (1.f + expf(-(iz.x + hz.x)));
        float n = tanhf(in_.x + r * hn.x);
        o.x = (1.f - z) * n + z * hd.x;
    }
    {
        float r = 1.f / (1.f + expf(-(ir.y + hr.y)));
        float z = 1.f / (1.f + expf(-(iz.y + hz.y)));
        float n = tanhf(in_.y + r * hn.y);
        o.y = (1.f - z) * n + z * hd.y;
    }
    {
        float r = 1.f / (1.f + expf(-(ir.z + hr.z)));
        float z = 1.f / (1.f + expf(-(iz.z + hz.z)));
        float n = tanhf(in_.z + r * hn.z);
        o.z = (1.f - z) * n + z * hd.z;
    }
    {
        float r = 1.f / (1.f + expf(-(ir.w + hr.w)));
        float z = 1.f / (1.f + expf(-(iz.w + hz.w)));
        float n = tanhf(in_.w + r * hn.w);
        o.w = (1.f - z) * n + z * hd.w;
    }
    newh[idx] = o;
}

// ---------------- fused lsm: each block computes its row's lse, then subtracts ----------------
__global__ void k_lsm_write(float* __restrict__ out,
                            const float* __restrict__ pmax, const float* __restrict__ psum) {
    int c = blockIdx.x;          // 8 chunks
    int b = blockIdx.y;
    __shared__ float red[8];
    __shared__ float s_lse;

    float m = -1e30f;
    for (int i = threadIdx.x; i < NBLK_OUT; i += 256) m = fmaxf(m, pmax[b * 512 + i]);
#pragma unroll
    for (int o = 16; o > 0; o >>= 1) m = fmaxf(m, __shfl_xor_sync(~0u, m, o));
    if ((threadIdx.x & 31) == 0) red[threadIdx.x >> 5] = m;
    __syncthreads();
    if (threadIdx.x == 0) {
        float t = red[0];
#pragma unroll
        for (int i = 1; i < 8; i++) t = fmaxf(t, red[i]);
        red[0] = t;
    }
    __syncthreads();
    float M = red[0];
    __syncthreads();
    float s = 0.f;
    for (int i = threadIdx.x; i < NBLK_OUT; i += 256)
        s += psum[b * 512 + i] * __expf(pmax[b * 512 + i] - M);
#pragma unroll
    for (int o = 16; o > 0; o >>= 1) s += __shfl_xor_sync(~0u, s, o);
    if ((threadIdx.x & 31) == 0) red[threadIdx.x >> 5] = s;
    __syncthreads();
    if (threadIdx.x == 0) {
        float t = 0.f;
#pragma unroll
        for (int i = 0; i < 8; i++) t += red[i];
        s_lse = M + logf(t);
    }
    __syncthreads();
    float L = s_lse;

    const int CH = (VV + 7) / 8;
    int start = c * CH;
    int end = min(start + CH, VV);
    float* row = out + (size_t)b * VV;
    for (int i = start + threadIdx.x; i < end; i += 256) row[i] -= L;
}

// ---------------- launch ----------------
extern "C" void kernel_launch(void* const* d_in, const int* in_sizes, int n_in,
                              void* d_out, int out_size) {
    const int*   ids    = (const int*)  d_in[0];
    const float* hidden = (const float*)d_in[1];
    const float* enc    = (const float*)d_in[2];
    const float* embW   = (const float*)d_in[3];
    const float* attnW  = (const float*)d_in[4];
    const float* attnb  = (const float*)d_in[5];
    const float* combW  = (const float*)d_in[6];
    const float* combb  = (const float*)d_in[7];
    const float* Wih    = (const float*)d_in[8];
    const float* Whh    = (const float*)d_in[9];
    const float* bih    = (const float*)d_in[10];
    const float* bhh    = (const float*)d_in[11];
    const float* outW   = (const float*)d_in[12];
    const float* outb   = (const float*)d_in[13];

    float* out  = (float*)d_out;
    float* newh = out + (size_t)BB * VV;

    float *p_attnapp, *p_x, *p_pa, *p_gh, *p_pmax, *p_psum;
    cudaGetSymbolAddress((void**)&p_attnapp, g_attnapp);
    cudaGetSymbolAddress((void**)&p_x, g_x);
    cudaGetSymbolAddress((void**)&p_pa, g_partA);
    cudaGetSymbolAddress((void**)&p_gh, g_partB);
    cudaGetSymbolAddress((void**)&p_pmax, g_pmax);
    cudaGetSymbolAddress((void**)&p_psum, g_psum);

    // 1. merged launch (single wave: 32 + 96 = 128 blocks):
    //    z=0 attn logits GEMM (4x8, split-K 8); z=1 gh GEMM (24x4, split-K 4)
    gemm_bf16s<<<dim3(24, 8, 2), 256>>>(embW, hidden, ids, EE, EE + HH, attnW,
                                        p_pa, LL, 256, 4, 8,
                                        hidden, Whh, p_gh, 3 * HH, 256, HH, 24, 4);

    // 2. fused softmax + attention context (8-split reduce)
    k_attnctx<<<dim3(8, BB), 256>>>(p_pa, attnb, enc, (float4*)p_attnapp);

    // 3. combine: cat(gather(emb), attn_applied) @ comb_W^T, split-K 8
    gemm_bf16s<<<dim3(8, 8, 1), 256>>>(embW, p_attnapp, ids, EE, EE + HH, combW,
                                       p_pa, EE, 256, 8, 8,
                                       nullptr, nullptr, nullptr, 0, 64, 0, 0, 0);
    k_combrelu<<<64, 256>>>((const float4*)p_pa, (const float4*)combb, (float4*)p_x);

    // 4. GRU gi = x @ Wih^T, split-K 4
    gemm_bf16s<<<dim3(24, 4, 1), 256>>>(p_x, nullptr, nullptr, HH, HH, Wih,
                                        p_pa, 3 * HH, 256, 24, 4,
                                        nullptr, nullptr, nullptr, 0, 64, 0, 0, 0);
    k_gru<<<64, 256>>>((const float4*)p_pa, (const float4*)p_gh,
                       (const float4*)bih, (const float4*)bhh,
                       (const float4*)hidden, (float4*)newh);

    // 5. output projection (2-MMA split-A bf16, 2 blocks/SM) + fused lsm partials
    k_outproj<<<NBLK_OUT, 256>>>(newh, outW, outb, out, p_pmax, p_psum);

    // 6. fused lse + subtract
    k_lsm_write<<<dim3(8, BB), 256>>>(out, p_pmax, p_psum);
}